// round 10
// baseline (speedup 1.0000x reference)
#include <cuda_runtime.h>
#include <cuda_fp16.h>
#include <cstdint>

// ---------------------------------------------------------------------------
// EdgeDense: z = x @ W + b  (N x 32, stored fp16), then
//            out[e] = w_e * (z[rows[e]] + z[cols[e]])   (fp32 out)
// N_NODES = 100000, IN = 128, OUT = 32, E = 1.6M
// GEMM via tf32 mma.sync (z^T tiles), edge kernel gather/scatter.
// ---------------------------------------------------------------------------

#define MAX_NODES 100000
#define IN_F 128
#define OUT_F 32

#define GB 128                  // gemm threads per block
#define NPB 128                 // nodes per block -> 782 blocks, single wave
#define SXS 36                  // x staging stride (floats): conflict-free
#define ZTS 40                  // epilogue z tile stride (halves): 80B rows

// z in fp16: 100000 * 32 * 2B = 6.4 MB (L2-resident). Device global.
__device__ __half2 g_zh[(size_t)MAX_NODES * (OUT_F / 2)];
// Index-dtype flag: 1 => indices are int64, 0 => indices are int32.
__device__ int g_idx64;

#define CVT_TF32(u, f) \
    asm("cvt.rna.tf32.f32 %0, %1;" : "=r"(u) : "f"(f))

// D(16x8,f32) += A(16x8,tf32,row) * B(8x8,tf32,col)
#define MMA_TF32(d, a, b0, b1) \
    asm("mma.sync.aligned.m16n8k8.row.col.f32.tf32.tf32.f32 " \
        "{%0,%1,%2,%3}, {%4,%5,%6,%7}, {%8,%9}, {%0,%1,%2,%3};" \
        : "+f"((d)[0]), "+f"((d)[1]), "+f"((d)[2]), "+f"((d)[3]) \
        : "r"((a)[0]), "r"((a)[1]), "r"((a)[2]), "r"((a)[3]), \
          "r"(b0), "r"(b1))

// ---------------------------------------------------------------------------
// GEMM (R9 version, measured 18.0us): z^T = W^T(32x128) @ x^T(128xN) with
// m16n8k8 tf32 MMA. A = W^T fragments prebuilt in smem (exact per-lane
// order, 1 LDS.128 per (mt,kt)). B = x staged per 32-k chunk (stride 36,
// conflict-free), cvt.rna.tf32 at staging (RZ would bias ~2^-10). Warp
// covers 32 outputs x 32 nodes; register double-buffered x prefetch hides
// LDG under MMAs. NPB=128 -> 782 blocks = one full wave.
// Fragment maps (g=lane>>2, t=lane&3):
//   a0=A[g][t] a1=A[g+8][t] a2=A[g][t+4] a3=A[g+8][t+4]
//   b0=B[t][g] b1=B[t+4][g]
//   d0=D[g][2t] d1=D[g][2t+1] d2=D[g+8][2t] d3=D[g+8][2t+1]
// Epilogue: bias, fp16, staged via smem for coalesced 16B stores.
// Block 0 runs the edge-index dtype probe (JAX x64-off hazard: int32 read
// as int64 words is >= 2^32 whenever the odd word != 0).
// ---------------------------------------------------------------------------
__global__ __launch_bounds__(GB)
void gemm_kernel(const float4* __restrict__ x4,
                 const float*  __restrict__ W,    // [128][32] row-major
                 const float*  __restrict__ b,    // [32]
                 __half2* __restrict__ zh,
                 int n_nodes,
                 const long long* __restrict__ idx_probe) {
    __shared__ unsigned sWf[2 * 16 * 32 * 4];     // 16 KB A fragments (tf32)
    __shared__ float sx[NPB * SXS];               // 18 KB x chunk / epilogue
    __shared__ int s_bad;

    int tid = threadIdx.x;
    int lane = tid & 31, wp = tid >> 5;           // wp 0..3
    int g = lane >> 2, t = lane & 3;
    int base = blockIdx.x * NPB;

    // Build A fragments: sWf[((mt*16+kt)*32+lane)*4 + r]
    for (int idx = tid; idx < 2 * 16 * 32; idx += GB) {
        int mt = idx >> 9;
        int rem = idx & 511;
        int kt = rem >> 5;
        int ln = rem & 31;
        int gg = ln >> 2, tt = ln & 3;
        int k0 = kt * 8, ob = mt * 16;
        float r0 = W[(k0 + tt) * OUT_F + ob + gg];
        float r1 = W[(k0 + tt) * OUT_F + ob + gg + 8];
        float r2 = W[(k0 + tt + 4) * OUT_F + ob + gg];
        float r3 = W[(k0 + tt + 4) * OUT_F + ob + gg + 8];
        unsigned u0, u1, u2, u3;
        CVT_TF32(u0, r0); CVT_TF32(u1, r1);
        CVT_TF32(u2, r2); CVT_TF32(u3, r3);
        *reinterpret_cast<uint4*>(&sWf[idx * 4]) = make_uint4(u0, u1, u2, u3);
    }
    if (blockIdx.x == 0 && tid == 0) s_bad = 0;

    if (blockIdx.x == 0) {
        long long v = idx_probe[tid];
        if (v < 0 || v >= (long long)n_nodes) atomicOr(&s_bad, 1);
    }

    // Staging geometry (fixed per thread): 8 float4 per chunk.
    int sn[8], sq[8], sgn[8];
    #pragma unroll
    for (int j = 0; j < 8; j++) {
        int i = j * GB + tid;
        sn[j] = i >> 3;                 // node 0..127
        sq[j] = i & 7;                  // float4 slot within 32-k chunk
        sgn[j] = base + sn[j];
    }

    // Prefetch chunk 0.
    float4 ld[8];
    #pragma unroll
    for (int j = 0; j < 8; j++) {
        ld[j] = make_float4(0.f, 0.f, 0.f, 0.f);
        if (sgn[j] < n_nodes)
            ld[j] = __ldg(&x4[(size_t)sgn[j] * (IN_F / 4) + sq[j]]);
    }

    float d[2][4][4];
    #pragma unroll
    for (int mt = 0; mt < 2; mt++)
        #pragma unroll
        for (int nt = 0; nt < 4; nt++)
            #pragma unroll
            for (int r = 0; r < 4; r++) d[mt][nt][r] = 0.f;

    unsigned* sxb = reinterpret_cast<unsigned*>(sx);

    #pragma unroll
    for (int c = 0; c < 4; c++) {
        #pragma unroll
        for (int j = 0; j < 8; j++) {
            unsigned u0, u1, u2, u3;
            CVT_TF32(u0, ld[j].x); CVT_TF32(u1, ld[j].y);
            CVT_TF32(u2, ld[j].z); CVT_TF32(u3, ld[j].w);
            *reinterpret_cast<uint4*>(&sxb[sn[j] * SXS + sq[j] * 4]) =
                make_uint4(u0, u1, u2, u3);
        }
        __syncthreads();

        if (c < 3) {
            #pragma unroll
            for (int j = 0; j < 8; j++) {
                ld[j] = make_float4(0.f, 0.f, 0.f, 0.f);
                if (sgn[j] < n_nodes)
                    ld[j] = __ldg(&x4[(size_t)sgn[j] * (IN_F / 4)
                                      + (c + 1) * 8 + sq[j]]);
            }
        }

        unsigned a[2][4][4];
        #pragma unroll
        for (int mt = 0; mt < 2; mt++)
            #pragma unroll
            for (int kt = 0; kt < 4; kt++)
                *reinterpret_cast<uint4*>(a[mt][kt]) =
                    *reinterpret_cast<const uint4*>(
                        &sWf[((mt * 16 + c * 4 + kt) * 32 + lane) * 4]);

        #pragma unroll
        for (int nt = 0; nt < 4; nt++) {
            int nl = wp * 32 + nt * 8 + g;
            #pragma unroll
            for (int kt = 0; kt < 4; kt++) {
                unsigned b0 = sxb[nl * SXS + kt * 8 + t];
                unsigned b1 = sxb[nl * SXS + kt * 8 + t + 4];
                MMA_TF32(d[0][nt], a[0][kt], b0, b1);
                MMA_TF32(d[1][nt], a[1][kt], b0, b1);
            }
        }
        __syncthreads();
    }

    // Epilogue: bias + fp16, stage via smem (sx reused as half zt[128][40]).
    float bias_v[4];
    bias_v[0] = __ldg(&b[g]);
    bias_v[1] = __ldg(&b[g + 8]);
    bias_v[2] = __ldg(&b[16 + g]);
    bias_v[3] = __ldg(&b[16 + g + 8]);

    __half* zt = reinterpret_cast<__half*>(sx);
    #pragma unroll
    for (int mt = 0; mt < 2; mt++) {
        #pragma unroll
        for (int nt = 0; nt < 4; nt++) {
            int n0 = wp * 32 + nt * 8 + 2 * t;
            int o0 = mt * 16 + g;
            zt[n0 * ZTS + o0]           = __float2half(d[mt][nt][0] + bias_v[mt * 2]);
            zt[(n0 + 1) * ZTS + o0]     = __float2half(d[mt][nt][1] + bias_v[mt * 2]);
            zt[n0 * ZTS + o0 + 8]       = __float2half(d[mt][nt][2] + bias_v[mt * 2 + 1]);
            zt[(n0 + 1) * ZTS + o0 + 8] = __float2half(d[mt][nt][3] + bias_v[mt * 2 + 1]);
        }
    }
    __syncwarp();

    #pragma unroll
    for (int p = 0; p < 4; p++) {
        int i = p * 32 + lane;
        int nl = wp * 32 + (i >> 2);
        int part = i & 3;
        int node = base + nl;
        if (node < n_nodes) {
            uint4 v = *reinterpret_cast<const uint4*>(&zt[nl * ZTS + part * 8]);
            *reinterpret_cast<uint4*>(
                reinterpret_cast<char*>(zh) + (size_t)node * 64 + part * 16) = v;
        }
    }

    if (blockIdx.x == 0) {
        __syncthreads();
        if (tid == 0) g_idx64 = s_bad ? 0 : 1;
    }
}

// ---------------------------------------------------------------------------
// Edge kernel: R8 launch shape (256-thr one-shot grid, measured 49.2us),
// with __launch_bounds__(256, 8) forcing <=32 regs so 8 CTAs/SM fit
// (R8 had 34 regs -> 7 CTAs -> occ capped at 87.5%, achieved 64%).
// The kernel is latency-limited with nothing saturated; occupancy is the
// cheapest lever. 8 lanes/edge, uint2 gathers (4 distinct z rows per gather
// instr -- measured optimum); 4 CONSECUTIVE edges per thread, vectorized
// index/val loads (1-2 LDG.128 each); stores 1 STG.128/lane/edge, streaming.
// ---------------------------------------------------------------------------
__global__ __launch_bounds__(256, 8)
void edge_kernel(const __half2* __restrict__ zh,
                 const void* __restrict__ rows_raw,
                 const void* __restrict__ cols_raw,
                 const float* __restrict__ vals,
                 float4* __restrict__ out,
                 int n_edges) {
    int gid = blockIdx.x * blockDim.x + threadIdx.x;
    int m = gid >> 3;
    int c = gid & 7;
    int eb = m * 4;
    if (eb >= n_edges) return;

    const uint2* zb = reinterpret_cast<const uint2*>(zh);

    if (eb + 3 < n_edges) {
        int r[4], cc[4];
        float w[4];
        if (g_idx64) {
            const int4* rp = (const int4*)rows_raw;
            const int4* cp = (const int4*)cols_raw;
            int4 ra = __ldcs(&rp[2 * m]), rb = __ldcs(&rp[2 * m + 1]);
            int4 ca = __ldcs(&cp[2 * m]), cb = __ldcs(&cp[2 * m + 1]);
            r[0] = ra.x; r[1] = ra.z; r[2] = rb.x; r[3] = rb.z;
            cc[0] = ca.x; cc[1] = ca.z; cc[2] = cb.x; cc[3] = cb.z;
        } else {
            int4 ra = __ldcs(&((const int4*)rows_raw)[m]);
            int4 ca = __ldcs(&((const int4*)cols_raw)[m]);
            r[0] = ra.x; r[1] = ra.y; r[2] = ra.z; r[3] = ra.w;
            cc[0] = ca.x; cc[1] = ca.y; cc[2] = ca.z; cc[3] = ca.w;
        }
        float4 wv = __ldcs(&((const float4*)vals)[m]);
        w[0] = wv.x; w[1] = wv.y; w[2] = wv.z; w[3] = wv.w;

        uint2 ga[4], gd[4];
        #pragma unroll
        for (int q = 0; q < 4; q++) {
            ga[q] = __ldg(&zb[(size_t)r[q] * 8 + c]);
            gd[q] = __ldg(&zb[(size_t)cc[q] * 8 + c]);
        }

        #pragma unroll
        for (int q = 0; q < 4; q++) {
            float2 fa0 = __half22float2(*reinterpret_cast<__half2*>(&ga[q].x));
            float2 fd0 = __half22float2(*reinterpret_cast<__half2*>(&gd[q].x));
            float2 fa1 = __half22float2(*reinterpret_cast<__half2*>(&ga[q].y));
            float2 fd1 = __half22float2(*reinterpret_cast<__half2*>(&gd[q].y));
            float4 o;
            o.x = w[q] * (fa0.x + fd0.x);
            o.y = w[q] * (fa0.y + fd0.y);
            o.z = w[q] * (fa1.x + fd1.x);
            o.w = w[q] * (fa1.y + fd1.y);
            __stcs(&out[(size_t)(eb + q) * 8 + c], o);
        }
    } else {
        // Tail: per-edge guarded scalar path.
        int sh = g_idx64;
        const int* rp = (const int*)rows_raw;
        const int* cp = (const int*)cols_raw;
        for (int q = 0; q < 4; q++) {
            int e = eb + q;
            if (e >= n_edges) break;
            int rr = __ldcs(&rp[e << sh]);
            int cl = __ldcs(&cp[e << sh]);
            float ww = __ldcs(&vals[e]);
            uint2 a = __ldg(&zb[(size_t)rr * 8 + c]);
            uint2 dd = __ldg(&zb[(size_t)cl * 8 + c]);
            float2 fa0 = __half22float2(*reinterpret_cast<__half2*>(&a.x));
            float2 fd0 = __half22float2(*reinterpret_cast<__half2*>(&dd.x));
            float2 fa1 = __half22float2(*reinterpret_cast<__half2*>(&a.y));
            float2 fd1 = __half22float2(*reinterpret_cast<__half2*>(&dd.y));
            float4 o;
            o.x = ww * (fa0.x + fd0.x);
            o.y = ww * (fa0.y + fd0.y);
            o.z = ww * (fa1.x + fd1.x);
            o.w = ww * (fa1.y + fd1.y);
            __stcs(&out[(size_t)e * 8 + c], o);
        }
    }
}

// ---------------------------------------------------------------------------
// Launch. Inputs (metadata order): x, W, b, edge_rows, edge_cols, edge_vals.
// ---------------------------------------------------------------------------
extern "C" void kernel_launch(void* const* d_in, const int* in_sizes, int n_in,
                              void* d_out, int out_size) {
    const float4* x4   = (const float4*)d_in[0];
    const float*  W    = (const float*)d_in[1];
    const float*  b    = (const float*)d_in[2];
    const void*   rows = d_in[3];
    const void*   cols = d_in[4];
    const float*  vals = (const float*)d_in[5];
    float4* out = (float4*)d_out;

    int n_nodes = in_sizes[0] / IN_F;
    int n_edges = in_sizes[3];

    __half2* zh = nullptr;
    cudaGetSymbolAddress((void**)&zh, g_zh);

    // 1) z = x @ W + b via tf32 MMA (+ index-dtype probe in block 0)
    int gemm_blocks = (n_nodes + NPB - 1) / NPB;   // 782: one full wave
    gemm_kernel<<<gemm_blocks, GB>>>(
        x4, W, b, zh, n_nodes, (const long long*)rows);

    // 2) out[e] = w_e * (z[r] + z[c]), 4 consecutive edges/thread,
    //    8 lanes/edge, 256-thr blocks (one-shot grid).
    int M = (n_edges + 3) >> 2;
    long long total = (long long)M * 8;
    int edge_blocks = (int)((total + 255) / 256);
    edge_kernel<<<edge_blocks, 256>>>(zh, rows, cols, vals, out, n_edges);
}

// round 11
// speedup vs baseline: 1.3436x; 1.3436x over previous
#include <cuda_runtime.h>
#include <cuda_fp16.h>
#include <cstdint>

// ---------------------------------------------------------------------------
// EdgeDense: z = x @ W + b  (N x 32, stored fp16), then
//            out[e] = w_e * (z[rows[e]] + z[cols[e]])   (fp32 out)
// N_NODES = 100000, IN = 128, OUT = 32, E = 1.6M
// GEMM via tf32 mma.sync (z^T tiles), edge kernel gather/scatter.
// ---------------------------------------------------------------------------

#define MAX_NODES 100000
#define IN_F 128
#define OUT_F 32

#define GB 128                  // gemm threads per block
#define NPB 128                 // nodes per block -> 782 blocks, single wave
#define SXS 36                  // x staging stride (floats): conflict-free
#define ZTS 40                  // epilogue z tile stride (halves): 80B rows

// z in fp16: 100000 * 32 * 2B = 6.4 MB (L2-resident). Device global.
__device__ __half2 g_zh[(size_t)MAX_NODES * (OUT_F / 2)];
// Index-dtype flag: 1 => indices are int64, 0 => indices are int32.
__device__ int g_idx64;

#define CVT_TF32(u, f) \
    asm("cvt.rna.tf32.f32 %0, %1;" : "=r"(u) : "f"(f))

// D(16x8,f32) += A(16x8,tf32,row) * B(8x8,tf32,col)
#define MMA_TF32(d, a, b0, b1) \
    asm("mma.sync.aligned.m16n8k8.row.col.f32.tf32.tf32.f32 " \
        "{%0,%1,%2,%3}, {%4,%5,%6,%7}, {%8,%9}, {%0,%1,%2,%3};" \
        : "+f"((d)[0]), "+f"((d)[1]), "+f"((d)[2]), "+f"((d)[3]) \
        : "r"((a)[0]), "r"((a)[1]), "r"((a)[2]), "r"((a)[3]), \
          "r"(b0), "r"(b1))

// ---------------------------------------------------------------------------
// GEMM (R9 version, measured 18.0us -- unchanged): z^T = W^T(32x128) @
// x^T(128xN) with m16n8k8 tf32 MMA. A = W^T fragments prebuilt in smem
// (exact per-lane order, 1 LDS.128 per (mt,kt)). B = x staged per 32-k
// chunk (stride 36, conflict-free), cvt.rna.tf32 at staging. Warp covers
// 32 outputs x 32 nodes; register double-buffered x prefetch hides LDG
// under MMAs. NPB=128 -> 782 blocks = one full wave (6 CTAs/SM).
// Fragment maps (g=lane>>2, t=lane&3):
//   a0=A[g][t] a1=A[g+8][t] a2=A[g][t+4] a3=A[g+8][t+4]
//   b0=B[t][g] b1=B[t+4][g]
//   d0=D[g][2t] d1=D[g][2t+1] d2=D[g+8][2t] d3=D[g+8][2t+1]
// Epilogue: bias, fp16, staged via smem for coalesced 16B stores.
// Block 0 runs the edge-index dtype probe (JAX x64-off hazard: int32 read
// as int64 words is >= 2^32 whenever the odd word != 0).
// ---------------------------------------------------------------------------
__global__ __launch_bounds__(GB)
void gemm_kernel(const float4* __restrict__ x4,
                 const float*  __restrict__ W,    // [128][32] row-major
                 const float*  __restrict__ b,    // [32]
                 __half2* __restrict__ zh,
                 int n_nodes,
                 const long long* __restrict__ idx_probe) {
    __shared__ unsigned sWf[2 * 16 * 32 * 4];     // 16 KB A fragments (tf32)
    __shared__ float sx[NPB * SXS];               // 18 KB x chunk / epilogue
    __shared__ int s_bad;

    int tid = threadIdx.x;
    int lane = tid & 31, wp = tid >> 5;           // wp 0..3
    int g = lane >> 2, t = lane & 3;
    int base = blockIdx.x * NPB;

    // Build A fragments: sWf[((mt*16+kt)*32+lane)*4 + r]
    for (int idx = tid; idx < 2 * 16 * 32; idx += GB) {
        int mt = idx >> 9;
        int rem = idx & 511;
        int kt = rem >> 5;
        int ln = rem & 31;
        int gg = ln >> 2, tt = ln & 3;
        int k0 = kt * 8, ob = mt * 16;
        float r0 = W[(k0 + tt) * OUT_F + ob + gg];
        float r1 = W[(k0 + tt) * OUT_F + ob + gg + 8];
        float r2 = W[(k0 + tt + 4) * OUT_F + ob + gg];
        float r3 = W[(k0 + tt + 4) * OUT_F + ob + gg + 8];
        unsigned u0, u1, u2, u3;
        CVT_TF32(u0, r0); CVT_TF32(u1, r1);
        CVT_TF32(u2, r2); CVT_TF32(u3, r3);
        *reinterpret_cast<uint4*>(&sWf[idx * 4]) = make_uint4(u0, u1, u2, u3);
    }
    if (blockIdx.x == 0 && tid == 0) s_bad = 0;

    if (blockIdx.x == 0) {
        long long v = idx_probe[tid];
        if (v < 0 || v >= (long long)n_nodes) atomicOr(&s_bad, 1);
    }

    // Staging geometry (fixed per thread): 8 float4 per chunk.
    int sn[8], sq[8], sgn[8];
    #pragma unroll
    for (int j = 0; j < 8; j++) {
        int i = j * GB + tid;
        sn[j] = i >> 3;                 // node 0..127
        sq[j] = i & 7;                  // float4 slot within 32-k chunk
        sgn[j] = base + sn[j];
    }

    // Prefetch chunk 0.
    float4 ld[8];
    #pragma unroll
    for (int j = 0; j < 8; j++) {
        ld[j] = make_float4(0.f, 0.f, 0.f, 0.f);
        if (sgn[j] < n_nodes)
            ld[j] = __ldg(&x4[(size_t)sgn[j] * (IN_F / 4) + sq[j]]);
    }

    float d[2][4][4];
    #pragma unroll
    for (int mt = 0; mt < 2; mt++)
        #pragma unroll
        for (int nt = 0; nt < 4; nt++)
            #pragma unroll
            for (int r = 0; r < 4; r++) d[mt][nt][r] = 0.f;

    unsigned* sxb = reinterpret_cast<unsigned*>(sx);

    #pragma unroll
    for (int c = 0; c < 4; c++) {
        #pragma unroll
        for (int j = 0; j < 8; j++) {
            unsigned u0, u1, u2, u3;
            CVT_TF32(u0, ld[j].x); CVT_TF32(u1, ld[j].y);
            CVT_TF32(u2, ld[j].z); CVT_TF32(u3, ld[j].w);
            *reinterpret_cast<uint4*>(&sxb[sn[j] * SXS + sq[j] * 4]) =
                make_uint4(u0, u1, u2, u3);
        }
        __syncthreads();

        if (c < 3) {
            #pragma unroll
            for (int j = 0; j < 8; j++) {
                ld[j] = make_float4(0.f, 0.f, 0.f, 0.f);
                if (sgn[j] < n_nodes)
                    ld[j] = __ldg(&x4[(size_t)sgn[j] * (IN_F / 4)
                                      + (c + 1) * 8 + sq[j]]);
            }
        }

        unsigned a[2][4][4];
        #pragma unroll
        for (int mt = 0; mt < 2; mt++)
            #pragma unroll
            for (int kt = 0; kt < 4; kt++)
                *reinterpret_cast<uint4*>(a[mt][kt]) =
                    *reinterpret_cast<const uint4*>(
                        &sWf[((mt * 16 + c * 4 + kt) * 32 + lane) * 4]);

        #pragma unroll
        for (int nt = 0; nt < 4; nt++) {
            int nl = wp * 32 + nt * 8 + g;
            #pragma unroll
            for (int kt = 0; kt < 4; kt++) {
                unsigned b0 = sxb[nl * SXS + kt * 8 + t];
                unsigned b1 = sxb[nl * SXS + kt * 8 + t + 4];
                MMA_TF32(d[0][nt], a[0][kt], b0, b1);
                MMA_TF32(d[1][nt], a[1][kt], b0, b1);
            }
        }
        __syncthreads();
    }

    // Epilogue: bias + fp16, stage via smem (sx reused as half zt[128][40]).
    float bias_v[4];
    bias_v[0] = __ldg(&b[g]);
    bias_v[1] = __ldg(&b[g + 8]);
    bias_v[2] = __ldg(&b[16 + g]);
    bias_v[3] = __ldg(&b[16 + g + 8]);

    __half* zt = reinterpret_cast<__half*>(sx);
    #pragma unroll
    for (int mt = 0; mt < 2; mt++) {
        #pragma unroll
        for (int nt = 0; nt < 4; nt++) {
            int n0 = wp * 32 + nt * 8 + 2 * t;
            int o0 = mt * 16 + g;
            zt[n0 * ZTS + o0]           = __float2half(d[mt][nt][0] + bias_v[mt * 2]);
            zt[(n0 + 1) * ZTS + o0]     = __float2half(d[mt][nt][1] + bias_v[mt * 2]);
            zt[n0 * ZTS + o0 + 8]       = __float2half(d[mt][nt][2] + bias_v[mt * 2 + 1]);
            zt[(n0 + 1) * ZTS + o0 + 8] = __float2half(d[mt][nt][3] + bias_v[mt * 2 + 1]);
        }
    }
    __syncwarp();

    #pragma unroll
    for (int p = 0; p < 4; p++) {
        int i = p * 32 + lane;
        int nl = wp * 32 + (i >> 2);
        int part = i & 3;
        int node = base + nl;
        if (node < n_nodes) {
            uint4 v = *reinterpret_cast<const uint4*>(&zt[nl * ZTS + part * 8]);
            *reinterpret_cast<uint4*>(
                reinterpret_cast<char*>(zh) + (size_t)node * 64 + part * 16) = v;
        }
    }

    if (blockIdx.x == 0) {
        __syncthreads();
        if (tid == 0) g_idx64 = s_bad ? 0 : 1;
    }
}

// ---------------------------------------------------------------------------
// Edge kernel: exact R8 configuration (measured 49.2us; 34 regs, occ 64%,
// one-shot 256-thr grid -- both occupancy "fixes" regressed, so the
// scheduler shape is left alone). 8 lanes per edge, uint2 gathers (4
// distinct z rows per gather instr); 4 CONSECUTIVE edges per thread with
// vectorized index/val loads (1-2 LDG.128 each); front-batched gathers
// (MLP=8); stores 1 STG.128/lane/edge, streaming.
// ONE isolated change vs R8: gathers use __ldcg (skip L1 fill -- z's L1
// hit rate is ~3.5%, fills are pure L1 bandwidth overhead).
// ---------------------------------------------------------------------------
__global__ __launch_bounds__(256)
void edge_kernel(const __half2* __restrict__ zh,
                 const void* __restrict__ rows_raw,
                 const void* __restrict__ cols_raw,
                 const float* __restrict__ vals,
                 float4* __restrict__ out,
                 int n_edges) {
    int gid = blockIdx.x * blockDim.x + threadIdx.x;
    int m = gid >> 3;
    int c = gid & 7;
    int eb = m * 4;
    if (eb >= n_edges) return;

    const uint2* zb = reinterpret_cast<const uint2*>(zh);

    if (eb + 3 < n_edges) {
        int r[4], cc[4];
        float w[4];
        if (g_idx64) {
            const int4* rp = (const int4*)rows_raw;
            const int4* cp = (const int4*)cols_raw;
            int4 ra = __ldcs(&rp[2 * m]), rb = __ldcs(&rp[2 * m + 1]);
            int4 ca = __ldcs(&cp[2 * m]), cb = __ldcs(&cp[2 * m + 1]);
            r[0] = ra.x; r[1] = ra.z; r[2] = rb.x; r[3] = rb.z;
            cc[0] = ca.x; cc[1] = ca.z; cc[2] = cb.x; cc[3] = cb.z;
        } else {
            int4 ra = __ldcs(&((const int4*)rows_raw)[m]);
            int4 ca = __ldcs(&((const int4*)cols_raw)[m]);
            r[0] = ra.x; r[1] = ra.y; r[2] = ra.z; r[3] = ra.w;
            cc[0] = ca.x; cc[1] = ca.y; cc[2] = ca.z; cc[3] = ca.w;
        }
        float4 wv = __ldcs(&((const float4*)vals)[m]);
        w[0] = wv.x; w[1] = wv.y; w[2] = wv.z; w[3] = wv.w;

        uint2 ga[4], gd[4];
        #pragma unroll
        for (int q = 0; q < 4; q++) {
            ga[q] = __ldcg(&zb[(size_t)r[q] * 8 + c]);
            gd[q] = __ldcg(&zb[(size_t)cc[q] * 8 + c]);
        }

        #pragma unroll
        for (int q = 0; q < 4; q++) {
            float2 fa0 = __half22float2(*reinterpret_cast<__half2*>(&ga[q].x));
            float2 fd0 = __half22float2(*reinterpret_cast<__half2*>(&gd[q].x));
            float2 fa1 = __half22float2(*reinterpret_cast<__half2*>(&ga[q].y));
            float2 fd1 = __half22float2(*reinterpret_cast<__half2*>(&gd[q].y));
            float4 o;
            o.x = w[q] * (fa0.x + fd0.x);
            o.y = w[q] * (fa0.y + fd0.y);
            o.z = w[q] * (fa1.x + fd1.x);
            o.w = w[q] * (fa1.y + fd1.y);
            __stcs(&out[(size_t)(eb + q) * 8 + c], o);
        }
    } else {
        // Tail: per-edge guarded scalar path.
        int sh = g_idx64;
        const int* rp = (const int*)rows_raw;
        const int* cp = (const int*)cols_raw;
        for (int q = 0; q < 4; q++) {
            int e = eb + q;
            if (e >= n_edges) break;
            int rr = __ldcs(&rp[e << sh]);
            int cl = __ldcs(&cp[e << sh]);
            float ww = __ldcs(&vals[e]);
            uint2 a = __ldcg(&zb[(size_t)rr * 8 + c]);
            uint2 dd = __ldcg(&zb[(size_t)cl * 8 + c]);
            float2 fa0 = __half22float2(*reinterpret_cast<__half2*>(&a.x));
            float2 fd0 = __half22float2(*reinterpret_cast<__half2*>(&dd.x));
            float2 fa1 = __half22float2(*reinterpret_cast<__half2*>(&a.y));
            float2 fd1 = __half22float2(*reinterpret_cast<__half2*>(&dd.y));
            float4 o;
            o.x = ww * (fa0.x + fd0.x);
            o.y = ww * (fa0.y + fd0.y);
            o.z = ww * (fa1.x + fd1.x);
            o.w = ww * (fa1.y + fd1.y);
            __stcs(&out[(size_t)e * 8 + c], o);
        }
    }
}

// ---------------------------------------------------------------------------
// Launch. Inputs (metadata order): x, W, b, edge_rows, edge_cols, edge_vals.
// ---------------------------------------------------------------------------
extern "C" void kernel_launch(void* const* d_in, const int* in_sizes, int n_in,
                              void* d_out, int out_size) {
    const float4* x4   = (const float4*)d_in[0];
    const float*  W    = (const float*)d_in[1];
    const float*  b    = (const float*)d_in[2];
    const void*   rows = d_in[3];
    const void*   cols = d_in[4];
    const float*  vals = (const float*)d_in[5];
    float4* out = (float4*)d_out;

    int n_nodes = in_sizes[0] / IN_F;
    int n_edges = in_sizes[3];

    __half2* zh = nullptr;
    cudaGetSymbolAddress((void**)&zh, g_zh);

    // 1) z = x @ W + b via tf32 MMA (+ index-dtype probe in block 0)
    int gemm_blocks = (n_nodes + NPB - 1) / NPB;   // 782: one full wave
    gemm_kernel<<<gemm_blocks, GB>>>(
        x4, W, b, zh, n_nodes, (const long long*)rows);

    // 2) out[e] = w_e * (z[r] + z[c]), 4 consecutive edges/thread,
    //    8 lanes/edge, 256-thr blocks (one-shot grid, R8 shape).
    int M = (n_edges + 3) >> 2;
    long long total = (long long)M * 8;
    int edge_blocks = (int)((total + 255) / 256);
    edge_kernel<<<edge_blocks, 256>>>(zh, rows, cols, vals, out, n_edges);
}

// round 12
// speedup vs baseline: 1.3755x; 1.0237x over previous
#include <cuda_runtime.h>
#include <cuda_fp16.h>
#include <cstdint>

// ---------------------------------------------------------------------------
// EdgeDense: z = x @ W + b  (N x 32, stored fp16), then
//            out[e] = w_e * (z[rows[e]] + z[cols[e]])   (fp32 out)
// N_NODES = 100000, IN = 128, OUT = 32, E = 1.6M
// GEMM via tf32 mma.sync (z^T tiles), edge kernel gather/scatter.
// ---------------------------------------------------------------------------

#define MAX_NODES 100000
#define IN_F 128
#define OUT_F 32

#define GB 256                  // gemm threads per block (8 warps)
#define NPB 128                 // nodes per block -> 782 blocks, single wave
#define SXS 36                  // x staging stride (floats): conflict-free
#define ZTS 40                  // epilogue z tile stride (halves): 80B rows

// z in fp16: 100000 * 32 * 2B = 6.4 MB (L2-resident). Device global.
__device__ __half2 g_zh[(size_t)MAX_NODES * (OUT_F / 2)];
// Index-dtype flag: 1 => indices are int64, 0 => indices are int32.
__device__ int g_idx64;

#define CVT_TF32(u, f) \
    asm("cvt.rna.tf32.f32 %0, %1;" : "=r"(u) : "f"(f))

// D(16x8,f32) += A(16x8,tf32,row) * B(8x8,tf32,col)
#define MMA_TF32(d, a, b0, b1) \
    asm("mma.sync.aligned.m16n8k8.row.col.f32.tf32.tf32.f32 " \
        "{%0,%1,%2,%3}, {%4,%5,%6,%7}, {%8,%9}, {%0,%1,%2,%3};" \
        : "+f"((d)[0]), "+f"((d)[1]), "+f"((d)[2]), "+f"((d)[3]) \
        : "r"((a)[0]), "r"((a)[1]), "r"((a)[2]), "r"((a)[3]), \
          "r"(b0), "r"(b1))

// ---------------------------------------------------------------------------
// GEMM: z^T = W^T(32x128) @ x^T(128xN), m16n8k8 tf32 MMA.
// R12 change: 256 threads (8 warps) at the SAME NPB=128 / smem 34.5KB.
// 6 CTAs/SM x 256 thr = 48 warps/SM (75% occ, was 37.5%) -- the kernel is
// latency/barrier-limited streaming (2.65 TB/s vs ~6 achievable), so
// resident warps are the binding resource. Each warp now covers 32 outputs
// x 16 nodes (2 mt x 2 nt tiles); per-thread staging halves (4 float4 per
// chunk); register pressure drops.
// A = W^T fragments prebuilt in smem (per-lane order, 1 LDS.128 each).
// B = x staged per 32-k chunk (stride 36, conflict-free), cvt.rna.tf32 at
// staging. Register double-buffered prefetch hides LDG under the MMAs.
// Fragment maps (g=lane>>2, t=lane&3):
//   a0=A[g][t] a1=A[g+8][t] a2=A[g][t+4] a3=A[g+8][t+4]
//   b0=B[t][g] b1=B[t+4][g]
//   d0=D[g][2t] d1=D[g][2t+1] d2=D[g+8][2t] d3=D[g+8][2t+1]
// Epilogue: bias, fp16, staged via smem for coalesced 16B stores.
// Block 0 runs the edge-index dtype probe (JAX x64-off hazard: int32 read
// as int64 words is >= 2^32 whenever the odd word != 0).
// ---------------------------------------------------------------------------
__global__ __launch_bounds__(GB)
void gemm_kernel(const float4* __restrict__ x4,
                 const float*  __restrict__ W,    // [128][32] row-major
                 const float*  __restrict__ b,    // [32]
                 __half2* __restrict__ zh,
                 int n_nodes,
                 const long long* __restrict__ idx_probe) {
    __shared__ unsigned sWf[2 * 16 * 32 * 4];     // 16 KB A fragments (tf32)
    __shared__ float sx[NPB * SXS];               // 18 KB x chunk / epilogue
    __shared__ int s_bad;

    int tid = threadIdx.x;
    int lane = tid & 31, wp = tid >> 5;           // wp 0..7
    int g = lane >> 2, t = lane & 3;
    int base = blockIdx.x * NPB;

    // Build A fragments: sWf[((mt*16+kt)*32+lane)*4 + r]
    for (int idx = tid; idx < 2 * 16 * 32; idx += GB) {
        int mt = idx >> 9;
        int rem = idx & 511;
        int kt = rem >> 5;
        int ln = rem & 31;
        int gg = ln >> 2, tt = ln & 3;
        int k0 = kt * 8, ob = mt * 16;
        float r0 = W[(k0 + tt) * OUT_F + ob + gg];
        float r1 = W[(k0 + tt) * OUT_F + ob + gg + 8];
        float r2 = W[(k0 + tt + 4) * OUT_F + ob + gg];
        float r3 = W[(k0 + tt + 4) * OUT_F + ob + gg + 8];
        unsigned u0, u1, u2, u3;
        CVT_TF32(u0, r0); CVT_TF32(u1, r1);
        CVT_TF32(u2, r2); CVT_TF32(u3, r3);
        *reinterpret_cast<uint4*>(&sWf[idx * 4]) = make_uint4(u0, u1, u2, u3);
    }
    if (blockIdx.x == 0 && tid == 0) s_bad = 0;

    if (blockIdx.x == 0) {
        long long v = idx_probe[tid];
        if (v < 0 || v >= (long long)n_nodes) atomicOr(&s_bad, 1);
    }

    // Staging geometry (fixed per thread): 4 float4 per chunk.
    int sn[4], sq[4], sgn[4];
    #pragma unroll
    for (int j = 0; j < 4; j++) {
        int i = j * GB + tid;
        sn[j] = i >> 3;                 // node 0..127
        sq[j] = i & 7;                  // float4 slot within 32-k chunk
        sgn[j] = base + sn[j];
    }

    // Prefetch chunk 0.
    float4 ld[4];
    #pragma unroll
    for (int j = 0; j < 4; j++) {
        ld[j] = make_float4(0.f, 0.f, 0.f, 0.f);
        if (sgn[j] < n_nodes)
            ld[j] = __ldg(&x4[(size_t)sgn[j] * (IN_F / 4) + sq[j]]);
    }

    float d[2][2][4];
    #pragma unroll
    for (int mt = 0; mt < 2; mt++)
        #pragma unroll
        for (int nt = 0; nt < 2; nt++)
            #pragma unroll
            for (int r = 0; r < 4; r++) d[mt][nt][r] = 0.f;

    unsigned* sxb = reinterpret_cast<unsigned*>(sx);

    #pragma unroll
    for (int c = 0; c < 4; c++) {
        // Scatter prefetched chunk (tf32-converted) into sx[node][k].
        #pragma unroll
        for (int j = 0; j < 4; j++) {
            unsigned u0, u1, u2, u3;
            CVT_TF32(u0, ld[j].x); CVT_TF32(u1, ld[j].y);
            CVT_TF32(u2, ld[j].z); CVT_TF32(u3, ld[j].w);
            *reinterpret_cast<uint4*>(&sxb[sn[j] * SXS + sq[j] * 4]) =
                make_uint4(u0, u1, u2, u3);
        }
        __syncthreads();

        // Prefetch next chunk (completes under the MMAs below).
        if (c < 3) {
            #pragma unroll
            for (int j = 0; j < 4; j++) {
                ld[j] = make_float4(0.f, 0.f, 0.f, 0.f);
                if (sgn[j] < n_nodes)
                    ld[j] = __ldg(&x4[(size_t)sgn[j] * (IN_F / 4)
                                      + (c + 1) * 8 + sq[j]]);
            }
        }

        // This chunk's A fragments (one LDS.128 each, conflict-free).
        unsigned a[2][4][4];
        #pragma unroll
        for (int mt = 0; mt < 2; mt++)
            #pragma unroll
            for (int kt = 0; kt < 4; kt++)
                *reinterpret_cast<uint4*>(a[mt][kt]) =
                    *reinterpret_cast<const uint4*>(
                        &sWf[((mt * 16 + c * 4 + kt) * 32 + lane) * 4]);

        #pragma unroll
        for (int nt = 0; nt < 2; nt++) {
            int nl = wp * 16 + nt * 8 + g;
            #pragma unroll
            for (int kt = 0; kt < 4; kt++) {
                unsigned b0 = sxb[nl * SXS + kt * 8 + t];
                unsigned b1 = sxb[nl * SXS + kt * 8 + t + 4];
                MMA_TF32(d[0][nt], a[0][kt], b0, b1);
                MMA_TF32(d[1][nt], a[1][kt], b0, b1);
            }
        }
        __syncthreads();   // compute done before next scatter reuses sx
    }

    // Epilogue: bias + fp16, stage via smem (sx reused as half zt[128][40]).
    float bias_v[4];
    bias_v[0] = __ldg(&b[g]);
    bias_v[1] = __ldg(&b[g + 8]);
    bias_v[2] = __ldg(&b[16 + g]);
    bias_v[3] = __ldg(&b[16 + g + 8]);

    __half* zt = reinterpret_cast<__half*>(sx);
    #pragma unroll
    for (int mt = 0; mt < 2; mt++) {
        #pragma unroll
        for (int nt = 0; nt < 2; nt++) {
            int n0 = wp * 16 + nt * 8 + 2 * t;
            int o0 = mt * 16 + g;
            zt[n0 * ZTS + o0]           = __float2half(d[mt][nt][0] + bias_v[mt * 2]);
            zt[(n0 + 1) * ZTS + o0]     = __float2half(d[mt][nt][1] + bias_v[mt * 2]);
            zt[n0 * ZTS + o0 + 8]       = __float2half(d[mt][nt][2] + bias_v[mt * 2 + 1]);
            zt[(n0 + 1) * ZTS + o0 + 8] = __float2half(d[mt][nt][3] + bias_v[mt * 2 + 1]);
        }
    }
    __syncthreads();

    // Coalesced store: 128 nodes x 64B, 2 x 16B per thread.
    #pragma unroll
    for (int p = 0; p < 2; p++) {
        int i = p * GB + tid;           // 0..511
        int nl = i >> 2;
        int part = i & 3;
        int node = base + nl;
        if (node < n_nodes) {
            uint4 v = *reinterpret_cast<const uint4*>(&zt[nl * ZTS + part * 8]);
            *reinterpret_cast<uint4*>(
                reinterpret_cast<char*>(zh) + (size_t)node * 64 + part * 16) = v;
        }
    }

    if (blockIdx.x == 0) {
        __syncthreads();
        if (tid == 0) g_idx64 = s_bad ? 0 : 1;
    }
}

// ---------------------------------------------------------------------------
// Edge kernel: byte-identical to R11 (measured 48.3us -- family optimum;
// all lane-width / occupancy / persistence perturbations regressed).
// 8 lanes per edge, uint2 __ldcg gathers (4 distinct z rows per gather
// instr; L1 fill skipped -- z's L1 hit rate ~3.5%); 4 CONSECUTIVE edges per
// thread with vectorized index/val loads; front-batched gathers (MLP=8);
// stores 1 STG.128/lane/edge, streaming.
// ---------------------------------------------------------------------------
__global__ __launch_bounds__(256)
void edge_kernel(const __half2* __restrict__ zh,
                 const void* __restrict__ rows_raw,
                 const void* __restrict__ cols_raw,
                 const float* __restrict__ vals,
                 float4* __restrict__ out,
                 int n_edges) {
    int gid = blockIdx.x * blockDim.x + threadIdx.x;
    int m = gid >> 3;
    int c = gid & 7;
    int eb = m * 4;
    if (eb >= n_edges) return;

    const uint2* zb = reinterpret_cast<const uint2*>(zh);

    if (eb + 3 < n_edges) {
        int r[4], cc[4];
        float w[4];
        if (g_idx64) {
            const int4* rp = (const int4*)rows_raw;
            const int4* cp = (const int4*)cols_raw;
            int4 ra = __ldcs(&rp[2 * m]), rb = __ldcs(&rp[2 * m + 1]);
            int4 ca = __ldcs(&cp[2 * m]), cb = __ldcs(&cp[2 * m + 1]);
            r[0] = ra.x; r[1] = ra.z; r[2] = rb.x; r[3] = rb.z;
            cc[0] = ca.x; cc[1] = ca.z; cc[2] = cb.x; cc[3] = cb.z;
        } else {
            int4 ra = __ldcs(&((const int4*)rows_raw)[m]);
            int4 ca = __ldcs(&((const int4*)cols_raw)[m]);
            r[0] = ra.x; r[1] = ra.y; r[2] = ra.z; r[3] = ra.w;
            cc[0] = ca.x; cc[1] = ca.y; cc[2] = ca.z; cc[3] = ca.w;
        }
        float4 wv = __ldcs(&((const float4*)vals)[m]);
        w[0] = wv.x; w[1] = wv.y; w[2] = wv.z; w[3] = wv.w;

        uint2 ga[4], gd[4];
        #pragma unroll
        for (int q = 0; q < 4; q++) {
            ga[q] = __ldcg(&zb[(size_t)r[q] * 8 + c]);
            gd[q] = __ldcg(&zb[(size_t)cc[q] * 8 + c]);
        }

        #pragma unroll
        for (int q = 0; q < 4; q++) {
            float2 fa0 = __half22float2(*reinterpret_cast<__half2*>(&ga[q].x));
            float2 fd0 = __half22float2(*reinterpret_cast<__half2*>(&gd[q].x));
            float2 fa1 = __half22float2(*reinterpret_cast<__half2*>(&ga[q].y));
            float2 fd1 = __half22float2(*reinterpret_cast<__half2*>(&gd[q].y));
            float4 o;
            o.x = w[q] * (fa0.x + fd0.x);
            o.y = w[q] * (fa0.y + fd0.y);
            o.z = w[q] * (fa1.x + fd1.x);
            o.w = w[q] * (fa1.y + fd1.y);
            __stcs(&out[(size_t)(eb + q) * 8 + c], o);
        }
    } else {
        // Tail: per-edge guarded scalar path.
        int sh = g_idx64;
        const int* rp = (const int*)rows_raw;
        const int* cp = (const int*)cols_raw;
        for (int q = 0; q < 4; q++) {
            int e = eb + q;
            if (e >= n_edges) break;
            int rr = __ldcs(&rp[e << sh]);
            int cl = __ldcs(&cp[e << sh]);
            float ww = __ldcs(&vals[e]);
            uint2 a = __ldcg(&zb[(size_t)rr * 8 + c]);
            uint2 dd = __ldcg(&zb[(size_t)cl * 8 + c]);
            float2 fa0 = __half22float2(*reinterpret_cast<__half2*>(&a.x));
            float2 fd0 = __half22float2(*reinterpret_cast<__half2*>(&dd.x));
            float2 fa1 = __half22float2(*reinterpret_cast<__half2*>(&a.y));
            float2 fd1 = __half22float2(*reinterpret_cast<__half2*>(&dd.y));
            float4 o;
            o.x = ww * (fa0.x + fd0.x);
            o.y = ww * (fa0.y + fd0.y);
            o.z = ww * (fa1.x + fd1.x);
            o.w = ww * (fa1.y + fd1.y);
            __stcs(&out[(size_t)e * 8 + c], o);
        }
    }
}

// ---------------------------------------------------------------------------
// Launch. Inputs (metadata order): x, W, b, edge_rows, edge_cols, edge_vals.
// ---------------------------------------------------------------------------
extern "C" void kernel_launch(void* const* d_in, const int* in_sizes, int n_in,
                              void* d_out, int out_size) {
    const float4* x4   = (const float4*)d_in[0];
    const float*  W    = (const float*)d_in[1];
    const float*  b    = (const float*)d_in[2];
    const void*   rows = d_in[3];
    const void*   cols = d_in[4];
    const float*  vals = (const float*)d_in[5];
    float4* out = (float4*)d_out;

    int n_nodes = in_sizes[0] / IN_F;
    int n_edges = in_sizes[3];

    __half2* zh = nullptr;
    cudaGetSymbolAddress((void**)&zh, g_zh);

    // 1) z = x @ W + b via tf32 MMA (+ index-dtype probe in block 0)
    int gemm_blocks = (n_nodes + NPB - 1) / NPB;   // 782
    gemm_kernel<<<gemm_blocks, GB>>>(
        x4, W, b, zh, n_nodes, (const long long*)rows);

    // 2) out[e] = w_e * (z[r] + z[c]), 4 consecutive edges/thread,
    //    8 lanes/edge, 256-thr blocks (one-shot grid).
    int M = (n_edges + 3) >> 2;
    long long total = (long long)M * 8;
    int edge_blocks = (int)((total + 255) / 256);
    edge_kernel<<<edge_blocks, 256>>>(zh, rows, cols, vals, out, n_edges);
}

// round 13
// speedup vs baseline: 1.3829x; 1.0054x over previous
#include <cuda_runtime.h>
#include <cuda_fp16.h>
#include <cstdint>

// ---------------------------------------------------------------------------
// EdgeDense: z = x @ W + b  (N x 32, stored fp16), then
//            out[e] = w_e * (z[rows[e]] + z[cols[e]])   (fp32 out)
// N_NODES = 100000, IN = 128, OUT = 32, E = 1.6M
// GEMM via tf32 mma.sync with cp.async double-buffered staging;
// edge kernel gather/scatter (config frozen since R11).
// ---------------------------------------------------------------------------

#define MAX_NODES 100000
#define IN_F 128
#define OUT_F 32

#define GB 256                  // gemm threads per block (8 warps)
#define NPB 128                 // nodes per block -> 782 blocks
#define SXS 36                  // x staging stride (floats): conflict-free
#define ZTS 40                  // epilogue z tile stride (halves): 80B rows

// z in fp16: 100000 * 32 * 2B = 6.4 MB (L2-resident). Device global.
__device__ __half2 g_zh[(size_t)MAX_NODES * (OUT_F / 2)];
// Index-dtype flag: 1 => indices are int64, 0 => indices are int32.
__device__ int g_idx64;

#define CVT_TF32(u, f) \
    asm("cvt.rna.tf32.f32 %0, %1;" : "=r"(u) : "f"(f))

// 16B async copy global->shared; src_sz=0 => zero-fill (no src read).
#define CP_ASYNC16(dst_s, src_g, src_sz) \
    asm volatile("cp.async.ca.shared.global [%0], [%1], 16, %2;" \
                 :: "r"(dst_s), "l"(src_g), "r"(src_sz))
#define CP_COMMIT() asm volatile("cp.async.commit_group;")
#define CP_WAIT0()  asm volatile("cp.async.wait_group 0;" ::: "memory")

// D(16x8,f32) += A(16x8,tf32,row) * B(8x8,tf32,col)
#define MMA_TF32(d, a, b0, b1) \
    asm("mma.sync.aligned.m16n8k8.row.col.f32.tf32.tf32.f32 " \
        "{%0,%1,%2,%3}, {%4,%5,%6,%7}, {%8,%9}, {%0,%1,%2,%3};" \
        : "+f"((d)[0]), "+f"((d)[1]), "+f"((d)[2]), "+f"((d)[3]) \
        : "r"((a)[0]), "r"((a)[1]), "r"((a)[2]), "r"((a)[3]), \
          "r"(b0), "r"(b1))

// ---------------------------------------------------------------------------
// GEMM: z^T = W^T(32x128) @ x^T(128xN), m16n8k8 tf32 MMA.
// R13 change: cp.async double-buffered x staging. Iteration =
//   wait_group 0 -> syncthreads -> issue next chunk cp.async -> compute.
// 4 barriers per CTA (was 8) and no LDG->reg->STS roundtrip: the copy is
// LDGSTS, pipelined behind the MMAs. tf32 cvt moves to the B-operand load
// (cvt.rna on the LDS result) -- bitwise-identical z to R12.
// Buffer-overwrite safety: prefetch(c+1) writes buf[(c+1)&1], last read at
// compute(c-1); the syncthreads in iteration c is ordered after every
// warp's compute(c-1), so the write cannot race the reads.
// A = W^T fragments prebuilt in smem (per-lane order, 1 LDS.128 each).
// Warp covers 32 outputs x 16 nodes (2 mt x 2 nt tiles).
// Fragment maps (g=lane>>2, t=lane&3):
//   a0=A[g][t] a1=A[g+8][t] a2=A[g][t+4] a3=A[g+8][t+4]
//   b0=B[t][g] b1=B[t+4][g]
//   d0=D[g][2t] d1=D[g][2t+1] d2=D[g+8][2t] d3=D[g+8][2t+1]
// Epilogue: bias, fp16, staged via smem (buffer 0 reused) for coalesced
// 16B stores. Block 0 runs the edge-index dtype probe (JAX x64-off hazard:
// int32 read as int64 words is >= 2^32 whenever the odd word != 0).
// ---------------------------------------------------------------------------
__global__ __launch_bounds__(GB)
void gemm_kernel(const float4* __restrict__ x4,
                 const float*  __restrict__ W,    // [128][32] row-major
                 const float*  __restrict__ b,    // [32]
                 __half2* __restrict__ zh,
                 int n_nodes,
                 const long long* __restrict__ idx_probe) {
    __shared__ unsigned sWf[2 * 16 * 32 * 4];     // 16 KB A fragments (tf32)
    __shared__ float sx[2][NPB * SXS];            // 2 x 18 KB x buffers
    __shared__ int s_bad;

    int tid = threadIdx.x;
    int lane = tid & 31, wp = tid >> 5;           // wp 0..7
    int g = lane >> 2, t = lane & 3;
    int base = blockIdx.x * NPB;

    // Build A fragments: sWf[((mt*16+kt)*32+lane)*4 + r]
    for (int idx = tid; idx < 2 * 16 * 32; idx += GB) {
        int mt = idx >> 9;
        int rem = idx & 511;
        int kt = rem >> 5;
        int ln = rem & 31;
        int gg = ln >> 2, tt = ln & 3;
        int k0 = kt * 8, ob = mt * 16;
        float r0 = W[(k0 + tt) * OUT_F + ob + gg];
        float r1 = W[(k0 + tt) * OUT_F + ob + gg + 8];
        float r2 = W[(k0 + tt + 4) * OUT_F + ob + gg];
        float r3 = W[(k0 + tt + 4) * OUT_F + ob + gg + 8];
        unsigned u0, u1, u2, u3;
        CVT_TF32(u0, r0); CVT_TF32(u1, r1);
        CVT_TF32(u2, r2); CVT_TF32(u3, r3);
        *reinterpret_cast<uint4*>(&sWf[idx * 4]) = make_uint4(u0, u1, u2, u3);
    }
    if (blockIdx.x == 0 && tid == 0) s_bad = 0;

    if (blockIdx.x == 0) {
        long long v = idx_probe[tid];
        if (v < 0 || v >= (long long)n_nodes) atomicOr(&s_bad, 1);
    }

    // Staging geometry (fixed per thread): 4 x 16B cp.async per chunk.
    int sn[4], sq[4];
    unsigned ssz[4];
    const float4* gsrc[4];
    #pragma unroll
    for (int j = 0; j < 4; j++) {
        int i = j * GB + tid;
        sn[j] = i >> 3;                 // node 0..127
        sq[j] = i & 7;                  // float4 slot within 32-k chunk
        int gn = base + sn[j];
        ssz[j] = (gn < n_nodes) ? 16u : 0u;   // zero-fill out-of-range nodes
        gsrc[j] = &x4[(size_t)(gn < n_nodes ? gn : 0) * (IN_F / 4) + sq[j]];
    }
    unsigned sdst[2][4];
    #pragma unroll
    for (int bu = 0; bu < 2; bu++)
        #pragma unroll
        for (int j = 0; j < 4; j++)
            sdst[bu][j] = (unsigned)__cvta_generic_to_shared(
                &sx[bu][sn[j] * SXS + sq[j] * 4]);

    // Issue chunk 0 into buffer 0.
    #pragma unroll
    for (int j = 0; j < 4; j++) CP_ASYNC16(sdst[0][j], gsrc[j], ssz[j]);
    CP_COMMIT();

    float d[2][2][4];
    #pragma unroll
    for (int mt = 0; mt < 2; mt++)
        #pragma unroll
        for (int nt = 0; nt < 2; nt++)
            #pragma unroll
            for (int r = 0; r < 4; r++) d[mt][nt][r] = 0.f;

    #pragma unroll
    for (int c = 0; c < 4; c++) {
        CP_WAIT0();
        __syncthreads();   // chunk c data visible; all warps past compute c-1

        // Issue next chunk (overlaps the MMAs below).
        if (c < 3) {
            #pragma unroll
            for (int j = 0; j < 4; j++)
                CP_ASYNC16(sdst[(c + 1) & 1][j],
                           gsrc[j] + (c + 1) * 8, ssz[j]);
            CP_COMMIT();
        }

        const float* xb = sx[c & 1];

        // This chunk's A fragments (one LDS.128 each, conflict-free).
        unsigned a[2][4][4];
        #pragma unroll
        for (int mt = 0; mt < 2; mt++)
            #pragma unroll
            for (int kt = 0; kt < 4; kt++)
                *reinterpret_cast<uint4*>(a[mt][kt]) =
                    *reinterpret_cast<const uint4*>(
                        &sWf[((mt * 16 + c * 4 + kt) * 32 + lane) * 4]);

        #pragma unroll
        for (int nt = 0; nt < 2; nt++) {
            int nl = wp * 16 + nt * 8 + g;
            #pragma unroll
            for (int kt = 0; kt < 4; kt++) {
                float f0 = xb[nl * SXS + kt * 8 + t];
                float f1 = xb[nl * SXS + kt * 8 + t + 4];
                unsigned b0, b1;
                CVT_TF32(b0, f0);
                CVT_TF32(b1, f1);
                MMA_TF32(d[0][nt], a[0][kt], b0, b1);
                MMA_TF32(d[1][nt], a[1][kt], b0, b1);
            }
        }
    }
    __syncthreads();   // all MMAs done before buffer 0 is reused as zt

    // Epilogue: bias + fp16, stage via smem (sx[0] reused, half zt[128][40]).
    float bias_v[4];
    bias_v[0] = __ldg(&b[g]);
    bias_v[1] = __ldg(&b[g + 8]);
    bias_v[2] = __ldg(&b[16 + g]);
    bias_v[3] = __ldg(&b[16 + g + 8]);

    __half* zt = reinterpret_cast<__half*>(sx[0]);
    #pragma unroll
    for (int mt = 0; mt < 2; mt++) {
        #pragma unroll
        for (int nt = 0; nt < 2; nt++) {
            int n0 = wp * 16 + nt * 8 + 2 * t;
            int o0 = mt * 16 + g;
            zt[n0 * ZTS + o0]           = __float2half(d[mt][nt][0] + bias_v[mt * 2]);
            zt[(n0 + 1) * ZTS + o0]     = __float2half(d[mt][nt][1] + bias_v[mt * 2]);
            zt[n0 * ZTS + o0 + 8]       = __float2half(d[mt][nt][2] + bias_v[mt * 2 + 1]);
            zt[(n0 + 1) * ZTS + o0 + 8] = __float2half(d[mt][nt][3] + bias_v[mt * 2 + 1]);
        }
    }
    __syncthreads();

    // Coalesced store: 128 nodes x 64B, 2 x 16B per thread.
    #pragma unroll
    for (int p = 0; p < 2; p++) {
        int i = p * GB + tid;           // 0..511
        int nl = i >> 2;
        int part = i & 3;
        int node = base + nl;
        if (node < n_nodes) {
            uint4 v = *reinterpret_cast<const uint4*>(&zt[nl * ZTS + part * 8]);
            *reinterpret_cast<uint4*>(
                reinterpret_cast<char*>(zh) + (size_t)node * 64 + part * 16) = v;
        }
    }

    if (blockIdx.x == 0) {
        __syncthreads();
        if (tid == 0) g_idx64 = s_bad ? 0 : 1;
    }
}

// ---------------------------------------------------------------------------
// Edge kernel: byte-identical to R11/R12 (measured 48.2us -- family
// optimum; all lane-width / occupancy / persistence perturbations
// regressed). 8 lanes per edge, uint2 __ldcg gathers (4 distinct z rows
// per gather instr; L1 fill skipped); 4 CONSECUTIVE edges per thread with
// vectorized index/val loads; front-batched gathers (MLP=8); stores
// 1 STG.128/lane/edge, streaming.
// ---------------------------------------------------------------------------
__global__ __launch_bounds__(256)
void edge_kernel(const __half2* __restrict__ zh,
                 const void* __restrict__ rows_raw,
                 const void* __restrict__ cols_raw,
                 const float* __restrict__ vals,
                 float4* __restrict__ out,
                 int n_edges) {
    int gid = blockIdx.x * blockDim.x + threadIdx.x;
    int m = gid >> 3;
    int c = gid & 7;
    int eb = m * 4;
    if (eb >= n_edges) return;

    const uint2* zb = reinterpret_cast<const uint2*>(zh);

    if (eb + 3 < n_edges) {
        int r[4], cc[4];
        float w[4];
        if (g_idx64) {
            const int4* rp = (const int4*)rows_raw;
            const int4* cp = (const int4*)cols_raw;
            int4 ra = __ldcs(&rp[2 * m]), rb = __ldcs(&rp[2 * m + 1]);
            int4 ca = __ldcs(&cp[2 * m]), cb = __ldcs(&cp[2 * m + 1]);
            r[0] = ra.x; r[1] = ra.z; r[2] = rb.x; r[3] = rb.z;
            cc[0] = ca.x; cc[1] = ca.z; cc[2] = cb.x; cc[3] = cb.z;
        } else {
            int4 ra = __ldcs(&((const int4*)rows_raw)[m]);
            int4 ca = __ldcs(&((const int4*)cols_raw)[m]);
            r[0] = ra.x; r[1] = ra.y; r[2] = ra.z; r[3] = ra.w;
            cc[0] = ca.x; cc[1] = ca.y; cc[2] = ca.z; cc[3] = ca.w;
        }
        float4 wv = __ldcs(&((const float4*)vals)[m]);
        w[0] = wv.x; w[1] = wv.y; w[2] = wv.z; w[3] = wv.w;

        uint2 ga[4], gd[4];
        #pragma unroll
        for (int q = 0; q < 4; q++) {
            ga[q] = __ldcg(&zb[(size_t)r[q] * 8 + c]);
            gd[q] = __ldcg(&zb[(size_t)cc[q] * 8 + c]);
        }

        #pragma unroll
        for (int q = 0; q < 4; q++) {
            float2 fa0 = __half22float2(*reinterpret_cast<__half2*>(&ga[q].x));
            float2 fd0 = __half22float2(*reinterpret_cast<__half2*>(&gd[q].x));
            float2 fa1 = __half22float2(*reinterpret_cast<__half2*>(&ga[q].y));
            float2 fd1 = __half22float2(*reinterpret_cast<__half2*>(&gd[q].y));
            float4 o;
            o.x = w[q] * (fa0.x + fd0.x);
            o.y = w[q] * (fa0.y + fd0.y);
            o.z = w[q] * (fa1.x + fd1.x);
            o.w = w[q] * (fa1.y + fd1.y);
            __stcs(&out[(size_t)(eb + q) * 8 + c], o);
        }
    } else {
        // Tail: per-edge guarded scalar path.
        int sh = g_idx64;
        const int* rp = (const int*)rows_raw;
        const int* cp = (const int*)cols_raw;
        for (int q = 0; q < 4; q++) {
            int e = eb + q;
            if (e >= n_edges) break;
            int rr = __ldcs(&rp[e << sh]);
            int cl = __ldcs(&cp[e << sh]);
            float ww = __ldcs(&vals[e]);
            uint2 a = __ldcg(&zb[(size_t)rr * 8 + c]);
            uint2 dd = __ldcg(&zb[(size_t)cl * 8 + c]);
            float2 fa0 = __half22float2(*reinterpret_cast<__half2*>(&a.x));
            float2 fd0 = __half22float2(*reinterpret_cast<__half2*>(&dd.x));
            float2 fa1 = __half22float2(*reinterpret_cast<__half2*>(&a.y));
            float2 fd1 = __half22float2(*reinterpret_cast<__half2*>(&dd.y));
            float4 o;
            o.x = ww * (fa0.x + fd0.x);
            o.y = ww * (fa0.y + fd0.y);
            o.z = ww * (fa1.x + fd1.x);
            o.w = ww * (fa1.y + fd1.y);
            __stcs(&out[(size_t)e * 8 + c], o);
        }
    }
}

// ---------------------------------------------------------------------------
// Launch. Inputs (metadata order): x, W, b, edge_rows, edge_cols, edge_vals.
// ---------------------------------------------------------------------------
extern "C" void kernel_launch(void* const* d_in, const int* in_sizes, int n_in,
                              void* d_out, int out_size) {
    const float4* x4   = (const float4*)d_in[0];
    const float*  W    = (const float*)d_in[1];
    const float*  b    = (const float*)d_in[2];
    const void*   rows = d_in[3];
    const void*   cols = d_in[4];
    const float*  vals = (const float*)d_in[5];
    float4* out = (float4*)d_out;

    int n_nodes = in_sizes[0] / IN_F;
    int n_edges = in_sizes[3];

    __half2* zh = nullptr;
    cudaGetSymbolAddress((void**)&zh, g_zh);

    // 1) z = x @ W + b via tf32 MMA + cp.async pipeline (+ dtype probe)
    int gemm_blocks = (n_nodes + NPB - 1) / NPB;   // 782
    gemm_kernel<<<gemm_blocks, GB>>>(
        x4, W, b, zh, n_nodes, (const long long*)rows);

    // 2) out[e] = w_e * (z[r] + z[c]), 4 consecutive edges/thread,
    //    8 lanes/edge, 256-thr blocks (one-shot grid).
    int M = (n_edges + 3) >> 2;
    long long total = (long long)M * 8;
    int edge_blocks = (int)((total + 255) / 256);
    edge_kernel<<<edge_blocks, 256>>>(zh, rows, cols, vals, out, n_edges);
}